// round 1
// baseline (speedup 1.0000x reference)
#include <cuda_runtime.h>
#include <cstdint>
#include <cstdio>

// Problem constants
#define BB   16
#define CC   128
#define C4C  32
#define NPIX 2304                      // H*W = 48*48
#define NT   18                        // NPIX / 128
#define PB   (NT*NT)                   // KQ tile-blocks per batch = 324
#define BN_EPS 1e-5f

static const size_t N2 = (size_t)NPIX * (size_t)NPIX;

// -------- scratch (device globals; no allocation allowed) --------
__device__ float g_K [BB * C4C * NPIX];
__device__ float g_Q [BB * C4C * NPIX];
__device__ float g_V [BB * CC  * NPIX];
__device__ float g_KQ[(size_t)BB * (size_t)NPIX * (size_t)NPIX]; // 340 MB
__device__ float g_pm[BB * PB];
__device__ float g_pl[BB * PB];
__device__ float g_M [BB];
__device__ float g_Z [BB];

// -------- packed f32x2 helpers (Blackwell PTX) --------
__device__ __forceinline__ unsigned long long pk2(float lo, float hi) {
    unsigned long long r;
    asm("mov.b64 %0, {%1,%2};" : "=l"(r) : "f"(lo), "f"(hi));
    return r;
}
__device__ __forceinline__ float2 up2(unsigned long long v) {
    float2 r;
    asm("mov.b64 {%0,%1}, %2;" : "=f"(r.x), "=f"(r.y) : "l"(v));
    return r;
}
__device__ __forceinline__ void fma2(unsigned long long& d,
                                     unsigned long long a,
                                     unsigned long long b) {
    asm("fma.rn.f32x2 %0, %1, %2, %0;" : "+l"(d) : "l"(a), "l"(b));
}

// ============================================================================
// conv128: Y[b,o,n] = relu( sum_c Wf[o,c]*X[b,c,n] + bias[o] ),  O = 128
// Block = 128x128 (o x n) tile, 256 threads, 8x8 micro via f32x2.
// grid: (NT, B)
// ============================================================================
__global__ void __launch_bounds__(256) conv128_kernel(
    const float* __restrict__ X, size_t xStride, int CIN,
    const float* __restrict__ W,
    const float* __restrict__ gam, const float* __restrict__ bet,
    const float* __restrict__ mean, const float* __restrict__ var,
    float* __restrict__ Y, size_t yStride)
{
    __shared__ __align__(16) float Ws[16][128];
    __shared__ __align__(16) float Xs[16][128];
    __shared__ float scale_s[128], bias_s[128];

    const int t  = threadIdx.x;
    const int b  = blockIdx.y;
    const int n0 = blockIdx.x * 128;

    if (t < 128) {
        float s = gam[t] * rsqrtf(var[t] + BN_EPS);
        scale_s[t] = s;
        bias_s[t]  = bet[t] - mean[t] * s;
    }
    __syncthreads();

    const float* Xb = X + (size_t)b * xStride + n0;
    const int ty = t >> 4, tx = t & 15;

    unsigned long long acc[8][4];
#pragma unroll
    for (int i = 0; i < 8; i++)
#pragma unroll
        for (int j = 0; j < 4; j++) acc[i][j] = 0ull;

    for (int c0 = 0; c0 < CIN; c0 += 16) {
#pragma unroll
        for (int i = t; i < 2048; i += 256) {
            int k = i >> 7, o = i & 127;
            Ws[k][o] = W[o * CIN + c0 + k] * scale_s[o];
        }
#pragma unroll
        for (int i = t; i < 2048; i += 256) {
            int k = i >> 7, n = i & 127;
            Xs[k][n] = Xb[(size_t)(c0 + k) * NPIX + n];
        }
        __syncthreads();

#pragma unroll 4
        for (int k = 0; k < 16; k++) {
            float4 a0 = *(const float4*)&Ws[k][ty * 8];
            float4 a1 = *(const float4*)&Ws[k][ty * 8 + 4];
            unsigned long long ad[8] = {
                pk2(a0.x, a0.x), pk2(a0.y, a0.y), pk2(a0.z, a0.z), pk2(a0.w, a0.w),
                pk2(a1.x, a1.x), pk2(a1.y, a1.y), pk2(a1.z, a1.z), pk2(a1.w, a1.w)};
            unsigned long long bv[4];
#pragma unroll
            for (int j = 0; j < 4; j++)
                bv[j] = *(const unsigned long long*)&Xs[k][tx * 8 + 2 * j];
#pragma unroll
            for (int i = 0; i < 8; i++)
#pragma unroll
                for (int j = 0; j < 4; j++) fma2(acc[i][j], ad[i], bv[j]);
        }
        __syncthreads();
    }

    float* Yb = Y + (size_t)b * yStride + n0 + tx * 8;
#pragma unroll
    for (int i = 0; i < 8; i++) {
        int o = ty * 8 + i;
        float bi = bias_s[o];
        float2 p0 = up2(acc[i][0]), p1 = up2(acc[i][1]);
        float2 p2 = up2(acc[i][2]), p3 = up2(acc[i][3]);
        float4 r0 = make_float4(fmaxf(p0.x + bi, 0.f), fmaxf(p0.y + bi, 0.f),
                                fmaxf(p1.x + bi, 0.f), fmaxf(p1.y + bi, 0.f));
        float4 r1 = make_float4(fmaxf(p2.x + bi, 0.f), fmaxf(p2.y + bi, 0.f),
                                fmaxf(p3.x + bi, 0.f), fmaxf(p3.y + bi, 0.f));
        *(float4*)&Yb[(size_t)o * NPIX]     = r0;
        *(float4*)&Yb[(size_t)o * NPIX + 4] = r1;
    }
}

// ============================================================================
// conv_kq: K/Q = relu(BN(w_kq @ x_en/x_de)),  O = 32, CIN = 128
// grid: (NT, B, 2)   z=0 -> K from x_en, z=1 -> Q from x_de
// ============================================================================
__global__ void __launch_bounds__(256) conv_kq_kernel(
    const float* __restrict__ Xen, const float* __restrict__ Xde,
    const float* __restrict__ W,
    const float* __restrict__ gam, const float* __restrict__ bet,
    const float* __restrict__ mean, const float* __restrict__ var)
{
    __shared__ __align__(16) float Ws[16][32];
    __shared__ __align__(16) float Xs[16][128];
    __shared__ float scale_s[32], bias_s[32];

    const int t  = threadIdx.x;
    const int b  = blockIdx.y;
    const int n0 = blockIdx.x * 128;
    const float* X = (blockIdx.z == 0) ? Xen : Xde;
    float* Y       = (blockIdx.z == 0) ? g_K : g_Q;

    if (t < 32) {
        float s = gam[t] * rsqrtf(var[t] + BN_EPS);
        scale_s[t] = s;
        bias_s[t]  = bet[t] - mean[t] * s;
    }
    __syncthreads();

    const float* Xb = X + (size_t)b * CC * NPIX + n0;
    const int ty = t >> 4, tx = t & 15;

    unsigned long long acc[2][4];
#pragma unroll
    for (int i = 0; i < 2; i++)
#pragma unroll
        for (int j = 0; j < 4; j++) acc[i][j] = 0ull;

    for (int c0 = 0; c0 < CC; c0 += 16) {
#pragma unroll
        for (int i = t; i < 512; i += 256) {
            int k = i >> 5, o = i & 31;
            Ws[k][o] = W[o * CC + c0 + k] * scale_s[o];
        }
#pragma unroll
        for (int i = t; i < 2048; i += 256) {
            int k = i >> 7, n = i & 127;
            Xs[k][n] = Xb[(size_t)(c0 + k) * NPIX + n];
        }
        __syncthreads();

#pragma unroll 4
        for (int k = 0; k < 16; k++) {
            float2 a = *(const float2*)&Ws[k][ty * 2];
            unsigned long long a0 = pk2(a.x, a.x);
            unsigned long long a1 = pk2(a.y, a.y);
            unsigned long long bv[4];
#pragma unroll
            for (int j = 0; j < 4; j++)
                bv[j] = *(const unsigned long long*)&Xs[k][tx * 8 + 2 * j];
#pragma unroll
            for (int j = 0; j < 4; j++) { fma2(acc[0][j], a0, bv[j]); fma2(acc[1][j], a1, bv[j]); }
        }
        __syncthreads();
    }

    float* Yb = Y + (size_t)b * C4C * NPIX + n0 + tx * 8;
#pragma unroll
    for (int i = 0; i < 2; i++) {
        int o = ty * 2 + i;
        float bi = bias_s[o];
        float2 p0 = up2(acc[i][0]), p1 = up2(acc[i][1]);
        float2 p2 = up2(acc[i][2]), p3 = up2(acc[i][3]);
        float4 r0 = make_float4(fmaxf(p0.x + bi, 0.f), fmaxf(p0.y + bi, 0.f),
                                fmaxf(p1.x + bi, 0.f), fmaxf(p1.y + bi, 0.f));
        float4 r1 = make_float4(fmaxf(p2.x + bi, 0.f), fmaxf(p2.y + bi, 0.f),
                                fmaxf(p3.x + bi, 0.f), fmaxf(p3.y + bi, 0.f));
        *(float4*)&Yb[(size_t)o * NPIX]     = r0;
        *(float4*)&Yb[(size_t)o * NPIX + 4] = r1;
    }
}

// ============================================================================
// kqgemm: KQ[b,n,m] = sum_k K[b,k,n]*Q[b,k,m]  (k depth = 32).
// Stores raw KQ tile to scratch and emits per-block (max, sumexp) partials.
// grid: (NT(m), NT(n), B), 256 threads, 128x128 tile, 8x8 micro (f32x2).
// ============================================================================
__global__ void __launch_bounds__(256) kqgemm_kernel()
{
    __shared__ __align__(16) float Ks[32][128];
    __shared__ __align__(16) float Qs[32][128];

    const int t  = threadIdx.x;
    const int b  = blockIdx.z;
    const int n0 = blockIdx.y * 128;
    const int m0 = blockIdx.x * 128;

    const float* Kb = g_K + (size_t)b * C4C * NPIX;
    const float* Qb = g_Q + (size_t)b * C4C * NPIX;

#pragma unroll
    for (int i = t; i < 4096; i += 256) {
        int k = i >> 7, c = i & 127;
        Ks[k][c] = Kb[(size_t)k * NPIX + n0 + c];
        Qs[k][c] = Qb[(size_t)k * NPIX + m0 + c];
    }
    __syncthreads();

    const int ty = t >> 4, tx = t & 15;
    unsigned long long acc[8][4];
#pragma unroll
    for (int i = 0; i < 8; i++)
#pragma unroll
        for (int j = 0; j < 4; j++) acc[i][j] = 0ull;

#pragma unroll 4
    for (int k = 0; k < 32; k++) {
        float4 a0 = *(const float4*)&Ks[k][ty * 8];
        float4 a1 = *(const float4*)&Ks[k][ty * 8 + 4];
        unsigned long long ad[8] = {
            pk2(a0.x, a0.x), pk2(a0.y, a0.y), pk2(a0.z, a0.z), pk2(a0.w, a0.w),
            pk2(a1.x, a1.x), pk2(a1.y, a1.y), pk2(a1.z, a1.z), pk2(a1.w, a1.w)};
        unsigned long long bv[4];
#pragma unroll
        for (int j = 0; j < 4; j++)
            bv[j] = *(const unsigned long long*)&Qs[k][tx * 8 + 2 * j];
#pragma unroll
        for (int i = 0; i < 8; i++)
#pragma unroll
            for (int j = 0; j < 4; j++) fma2(acc[i][j], ad[i], bv[j]);
    }

    // epilogue: unpack, store raw KQ, log-sum-exp partial
    float vals[8][8];
    float vmax = -1e30f;
#pragma unroll
    for (int i = 0; i < 8; i++) {
#pragma unroll
        for (int j = 0; j < 4; j++) {
            float2 p = up2(acc[i][j]);
            vals[i][2 * j]     = p.x;
            vals[i][2 * j + 1] = p.y;
            vmax = fmaxf(vmax, fmaxf(p.x, p.y));
        }
    }
#pragma unroll
    for (int i = 0; i < 8; i++) {
        size_t off = (size_t)b * N2 + (size_t)(n0 + ty * 8 + i) * NPIX + m0 + tx * 8;
        *(float4*)&g_KQ[off]     = make_float4(vals[i][0], vals[i][1], vals[i][2], vals[i][3]);
        *(float4*)&g_KQ[off + 4] = make_float4(vals[i][4], vals[i][5], vals[i][6], vals[i][7]);
    }
    float lt = 0.f;
#pragma unroll
    for (int i = 0; i < 8; i++)
#pragma unroll
        for (int j = 0; j < 8; j++) lt += __expf(vals[i][j] - vmax);

    __syncthreads();   // smem reuse
    float* sm = (float*)Ks;
    float* sl = (float*)Qs;
    sm[t] = vmax; sl[t] = lt;
    __syncthreads();
    for (int s = 128; s > 0; s >>= 1) {
        if (t < s) {
            float m1 = sm[t], m2 = sm[t + s], l1 = sl[t], l2 = sl[t + s];
            float M = fmaxf(m1, m2);
            sl[t] = l1 * __expf(m1 - M) + l2 * __expf(m2 - M);
            sm[t] = M;
        }
        __syncthreads();
    }
    if (t == 0) {
        int pb = blockIdx.y * NT + blockIdx.x;
        g_pm[b * PB + pb] = sm[0];
        g_pl[b * PB + pb] = sl[0];
    }
}

// ============================================================================
// combine: reduce PB partials -> per-batch (M, Z).  grid = B, 512 threads.
// ============================================================================
__global__ void __launch_bounds__(512) combine_kernel()
{
    __shared__ float sm[512], sl[512];
    const int b = blockIdx.x, t = threadIdx.x;
    float m = -INFINITY, l = 0.f;
    if (t < PB) { m = g_pm[b * PB + t]; l = g_pl[b * PB + t]; }
    sm[t] = m; sl[t] = l;
    __syncthreads();
    for (int s = 256; s > 0; s >>= 1) {
        if (t < s) {
            float m1 = sm[t], m2 = sm[t + s], l1 = sl[t], l2 = sl[t + s];
            float M = fmaxf(m1, m2);
            float L;
            if (M == -INFINITY) L = 0.f;
            else L = (m1 == -INFINITY ? 0.f : l1 * __expf(m1 - M))
                   + (m2 == -INFINITY ? 0.f : l2 * __expf(m2 - M));
            sm[t] = M; sl[t] = L;
        }
        __syncthreads();
    }
    if (t == 0) { g_M[b] = sm[0]; g_Z[b] = sl[0]; }
}

// ============================================================================
// feat: feat[b,c,n] = (1/Z) * sum_m V[b,c,m] * exp(KQ[b,n,m] - M)
// grid: (NT, B), 256 threads, 128(c) x 128(n) tile, m-chunks of 32.
// Writes to output channels [C, 2C).
// ============================================================================
__global__ void __launch_bounds__(256) feat_kernel(float* __restrict__ out)
{
    __shared__ __align__(16) float Vs[32][132];
    __shared__ __align__(16) float Ps[32][132];

    const int t  = threadIdx.x;
    const int b  = blockIdx.y;
    const int n0 = blockIdx.x * 128;

    const float Mb   = g_M[b];
    const float invZ = 1.f / g_Z[b];
    const int ty = t >> 4, tx = t & 15;

    unsigned long long acc[8][4];
#pragma unroll
    for (int i = 0; i < 8; i++)
#pragma unroll
        for (int j = 0; j < 4; j++) acc[i][j] = 0ull;

    const float* Vb  = g_V  + (size_t)b * CC * NPIX;
    const float* KQb = g_KQ + (size_t)b * N2 + (size_t)n0 * NPIX;

    for (int m0 = 0; m0 < NPIX; m0 += 32) {
#pragma unroll
        for (int i = t; i < 1024; i += 256) {
            int r = i >> 3, q = i & 7;   // r: 0..127 (c or nn), q: 0..7 (m-quad)
            float4 v = *(const float4*)&Vb[(size_t)r * NPIX + m0 + q * 4];
            Vs[q * 4 + 0][r] = v.x; Vs[q * 4 + 1][r] = v.y;
            Vs[q * 4 + 2][r] = v.z; Vs[q * 4 + 3][r] = v.w;
            float4 kq = *(const float4*)&KQb[(size_t)r * NPIX + m0 + q * 4];
            Ps[q * 4 + 0][r] = __expf(kq.x - Mb);
            Ps[q * 4 + 1][r] = __expf(kq.y - Mb);
            Ps[q * 4 + 2][r] = __expf(kq.z - Mb);
            Ps[q * 4 + 3][r] = __expf(kq.w - Mb);
        }
        __syncthreads();

#pragma unroll 4
        for (int k = 0; k < 32; k++) {
            float4 a0 = *(const float4*)&Vs[k][ty * 8];
            float4 a1 = *(const float4*)&Vs[k][ty * 8 + 4];
            unsigned long long ad[8] = {
                pk2(a0.x, a0.x), pk2(a0.y, a0.y), pk2(a0.z, a0.z), pk2(a0.w, a0.w),
                pk2(a1.x, a1.x), pk2(a1.y, a1.y), pk2(a1.z, a1.z), pk2(a1.w, a1.w)};
            unsigned long long bv[4];
#pragma unroll
            for (int j = 0; j < 4; j++)
                bv[j] = *(const unsigned long long*)&Ps[k][tx * 8 + 2 * j];
#pragma unroll
            for (int i = 0; i < 8; i++)
#pragma unroll
                for (int j = 0; j < 4; j++) fma2(acc[i][j], ad[i], bv[j]);
        }
        __syncthreads();
    }

    float* Ob = out + (size_t)b * (2 * CC) * NPIX + (size_t)CC * NPIX + n0 + tx * 8;
#pragma unroll
    for (int i = 0; i < 8; i++) {
        int c = ty * 8 + i;
        float2 p0 = up2(acc[i][0]), p1 = up2(acc[i][1]);
        float2 p2 = up2(acc[i][2]), p3 = up2(acc[i][3]);
        float4 r0 = make_float4(p0.x * invZ, p0.y * invZ, p1.x * invZ, p1.y * invZ);
        float4 r1 = make_float4(p2.x * invZ, p2.y * invZ, p3.x * invZ, p3.y * invZ);
        *(float4*)&Ob[(size_t)c * NPIX]     = r0;
        *(float4*)&Ob[(size_t)c * NPIX + 4] = r1;
    }
}

// ============================================================================
// launch
// ============================================================================
extern "C" void kernel_launch(void* const* d_in, const int* in_sizes, int n_in,
                              void* d_out, int out_size)
{
    const float* x_en   = (const float*)d_in[0];
    const float* x_de   = (const float*)d_in[1];
    const float* x_cat  = (const float*)d_in[2];
    const float* w_kq   = (const float*)d_in[3];
    const float* kq_g   = (const float*)d_in[4];
    const float* kq_b   = (const float*)d_in[5];
    const float* kq_m   = (const float*)d_in[6];
    const float* kq_v   = (const float*)d_in[7];
    const float* w_v    = (const float*)d_in[8];
    const float* v_g    = (const float*)d_in[9];
    const float* v_b    = (const float*)d_in[10];
    const float* v_m    = (const float*)d_in[11];
    const float* v_v    = (const float*)d_in[12];
    const float* w_red  = (const float*)d_in[13];
    const float* red_g  = (const float*)d_in[14];
    const float* red_b  = (const float*)d_in[15];
    const float* red_m  = (const float*)d_in[16];
    const float* red_v  = (const float*)d_in[17];
    float* out = (float*)d_out;

    float* pV = nullptr;
    cudaGetSymbolAddress((void**)&pV, g_V);

    const size_t twoCN = (size_t)2 * CC * NPIX;
    const size_t CN    = (size_t)CC * NPIX;

    // x = relu(BN(w_red @ x_cat)) -> output channels [0, C)
    conv128_kernel<<<dim3(NT, BB), 256>>>(x_cat, twoCN, 2 * CC, w_red,
                                          red_g, red_b, red_m, red_v,
                                          out, twoCN);
    // V = relu(BN(w_v @ x))  (reads x back from d_out first half)
    conv128_kernel<<<dim3(NT, BB), 256>>>(out, twoCN, CC, w_v,
                                          v_g, v_b, v_m, v_v,
                                          pV, CN);
    // K, Q
    conv_kq_kernel<<<dim3(NT, BB, 2), 256>>>(x_en, x_de, w_kq,
                                             kq_g, kq_b, kq_m, kq_v);
    // KQ + per-block logsumexp partials
    kqgemm_kernel<<<dim3(NT, NT, BB), 256>>>();
    // per-batch (M, Z)
    combine_kernel<<<BB, 512>>>();
    // feat -> output channels [C, 2C)
    feat_kernel<<<dim3(NT, BB), 256>>>(out);
}

// round 3
// speedup vs baseline: 1.7095x; 1.7095x over previous
#include <cuda_runtime.h>
#include <cstdint>

// Problem constants
#define BB   16
#define CC   128
#define C4C  32
#define NPIX 2304                      // H*W = 48*48
#define NT   18                        // NPIX / 128
#define PB   (NT*NT)                   // KQ tile-blocks per batch = 324
#define BN_EPS 1e-5f

// tcgen05 is only legal in arch-specific (sm_103a) compilation passes.
#if defined(__CUDA_ARCH_FEAT_SM103_ALL) || defined(__CUDA_ARCH_SPECIFIC__)
#define HAS_TC 1
#else
#define HAS_TC 0
#endif

static const size_t N2 = (size_t)NPIX * (size_t)NPIX;

// -------- scratch (device globals; no allocation allowed) --------
__device__ float g_K [BB * C4C * NPIX];
__device__ float g_Q [BB * C4C * NPIX];
__device__ float g_V [BB * CC  * NPIX];
__device__ float g_KQ[(size_t)BB * (size_t)NPIX * (size_t)NPIX]; // 340 MB
__device__ float g_pm[BB * PB];
__device__ float g_pl[BB * PB];
__device__ float g_M [BB];
__device__ float g_Z [BB];

// -------- packed f32x2 helpers (Blackwell PTX, family-portable) --------
__device__ __forceinline__ unsigned long long pk2(float lo, float hi) {
    unsigned long long r;
    asm("mov.b64 %0, {%1,%2};" : "=l"(r) : "f"(lo), "f"(hi));
    return r;
}
__device__ __forceinline__ float2 up2(unsigned long long v) {
    float2 r;
    asm("mov.b64 {%0,%1}, %2;" : "=f"(r.x), "=f"(r.y) : "l"(v));
    return r;
}
__device__ __forceinline__ void fma2(unsigned long long& d,
                                     unsigned long long a,
                                     unsigned long long b) {
    asm("fma.rn.f32x2 %0, %1, %2, %0;" : "+l"(d) : "l"(a), "l"(b));
}

__device__ __forceinline__ uint32_t smem_to_u32(const void* p) {
    uint32_t a;
    asm("{ .reg .u64 t; cvta.to.shared.u64 t, %1; cvt.u32.u64 %0, t; }"
        : "=r"(a) : "l"(p));
    return a;
}

#if HAS_TC
// -------- tcgen05 / mbarrier helpers (sm_103a-only pass) --------
__device__ __forceinline__ uint32_t elect_one_pred() {
    uint32_t pred;
    asm volatile(
        "{\n\t.reg .pred p;\n\t"
        "elect.sync _|p, 0xFFFFFFFF;\n\t"
        "selp.b32 %0, 1, 0, p;\n\t}"
        : "=r"(pred));
    return pred;
}
__device__ __forceinline__ float tf32r(float x) {
    uint32_t u;
    asm("cvt.rna.tf32.f32 %0, %1;" : "=r"(u) : "f"(x));
    return __uint_as_float(u);
}

#define MBARRIER_INIT(addr, cnt) \
    asm volatile("mbarrier.init.shared.b64 [%0], %1;" :: "r"(addr), "r"(cnt) : "memory")

#define MBARRIER_WAIT_PARITY(mbar_smem_addr, phase_parity) do { \
    uint32_t _mbar = (uint32_t)(mbar_smem_addr); \
    uint32_t _parity = (uint32_t)(phase_parity); \
    uint32_t _done; \
    asm volatile( \
        "{\n\t.reg .pred p;\n\t" \
        "mbarrier.try_wait.parity.acquire.cta.shared::cta.b64 p, [%1], %2;\n\t" \
        "selp.b32 %0, 1, 0, p;\n\t}" \
        : "=r"(_done) : "r"(_mbar), "r"(_parity) : "memory"); \
    if (!_done) { \
        asm volatile( \
            "{\n\t.reg .pred P1;\n\t" \
            "WAIT_LOOP_%=:\n\t" \
            "mbarrier.try_wait.parity.acquire.cta.shared::cta.b64 P1, [%0], %1, 0x989680;\n\t" \
            "@P1 bra.uni WAIT_DONE_%=;\n\t" \
            "bra.uni WAIT_LOOP_%=;\n\t" \
            "WAIT_DONE_%=:\n\t}" \
            :: "r"(_mbar), "r"(_parity) : "memory"); \
    } \
} while(0)

#define TCGEN05_ALLOC(smem_result_addr, nCols) \
    asm volatile("tcgen05.alloc.cta_group::1.sync.aligned.shared::cta.b32 [%0], %1;" \
        :: "r"((uint32_t)(smem_result_addr)), "r"((uint32_t)(nCols)) : "memory")
#define TCGEN05_DEALLOC(tmem_addr, nCols) \
    asm volatile("tcgen05.dealloc.cta_group::1.sync.aligned.b32 %0, %1;" \
        :: "r"(tmem_addr), "r"((uint32_t)(nCols)))
#define TCGEN05_COMMIT(mbar_smem_addr) \
    asm volatile("tcgen05.commit.cta_group::1.mbarrier::arrive::one.shared::cluster.b64 [%0];" \
        :: "r"((uint32_t)(mbar_smem_addr)) : "memory")
#define TCGEN05_FENCE_AFTER() \
    asm volatile("tcgen05.fence::after_thread_sync;" ::: "memory")
#define TCGEN05_WAIT_LD() \
    asm volatile("tcgen05.wait::ld.sync.aligned;" ::: "memory")

#define TCGEN05_LD_32X32B_X32(r, tmem_addr) \
    asm volatile( \
        "tcgen05.ld.sync.aligned.32x32b.x32.b32 " \
        "{%0, %1, %2, %3, %4, %5, %6, %7, " \
        " %8, %9, %10, %11, %12, %13, %14, %15, " \
        " %16, %17, %18, %19, %20, %21, %22, %23, " \
        " %24, %25, %26, %27, %28, %29, %30, %31}, [%32];" \
        : "=r"((r)[0]),  "=r"((r)[1]),  "=r"((r)[2]),  "=r"((r)[3]), \
          "=r"((r)[4]),  "=r"((r)[5]),  "=r"((r)[6]),  "=r"((r)[7]), \
          "=r"((r)[8]),  "=r"((r)[9]),  "=r"((r)[10]), "=r"((r)[11]), \
          "=r"((r)[12]), "=r"((r)[13]), "=r"((r)[14]), "=r"((r)[15]), \
          "=r"((r)[16]), "=r"((r)[17]), "=r"((r)[18]), "=r"((r)[19]), \
          "=r"((r)[20]), "=r"((r)[21]), "=r"((r)[22]), "=r"((r)[23]), \
          "=r"((r)[24]), "=r"((r)[25]), "=r"((r)[26]), "=r"((r)[27]), \
          "=r"((r)[28]), "=r"((r)[29]), "=r"((r)[30]), "=r"((r)[31]) \
        : "r"(tmem_addr))

// SW128 K-major SMEM descriptor (LBO=1, SBO=64, version=1, layout=SW128)
static constexpr uint64_t SMEM_DESC_BASE_SW128 =
    (uint64_t(2)  << 61) | (uint64_t(1) << 46) | (uint64_t(64) << 32) | (uint64_t(1) << 16);
#define MAKE_SMEM_DESC(base_addr) \
    (SMEM_DESC_BASE_SW128 | ((uint64_t)((base_addr) >> 4) & 0x3FFF))

// idesc kind::tf32: dtype=F32(1)@4, atype=TF32(2)@7, btype=TF32(2)@10,
// N>>3 @17, M>>4 @24  (M=128, N=128)
static constexpr uint32_t IDESC_TF32 =
    (1u << 4) | (2u << 7) | (2u << 10) | ((128u / 8) << 17) | ((128u / 16) << 24);

__device__ __forceinline__ void mma_tf32_ss(uint32_t d_tmem, uint64_t a_desc,
                                            uint64_t b_desc, uint32_t idesc,
                                            uint32_t enable) {
    asm volatile(
        "{\n\t.reg .pred p;\n\t"
        "setp.ne.u32 p, %5, 0;\n\t"
        "tcgen05.mma.cta_group::1.kind::tf32 [%0], %1, %2, %3, {%4, %4, %4, %4}, p;\n\t}"
        :: "r"(d_tmem), "l"(a_desc), "l"(b_desc), "r"(idesc), "r"(0u), "r"(enable)
        : "memory");
}
#endif // HAS_TC

// ============================================================================
// conv128: Y[b,o,n] = relu( sum_c Wf[o,c]*X[b,c,n] + bias[o] ),  O = 128
// ============================================================================
__global__ void __launch_bounds__(256) conv128_kernel(
    const float* __restrict__ X, size_t xStride, int CIN,
    const float* __restrict__ W,
    const float* __restrict__ gam, const float* __restrict__ bet,
    const float* __restrict__ mean, const float* __restrict__ var,
    float* __restrict__ Y, size_t yStride)
{
    __shared__ __align__(16) float Ws[16][128];
    __shared__ __align__(16) float Xs[16][128];
    __shared__ float scale_s[128], bias_s[128];

    const int t  = threadIdx.x;
    const int b  = blockIdx.y;
    const int n0 = blockIdx.x * 128;

    if (t < 128) {
        float s = gam[t] * rsqrtf(var[t] + BN_EPS);
        scale_s[t] = s;
        bias_s[t]  = bet[t] - mean[t] * s;
    }
    __syncthreads();

    const float* Xb = X + (size_t)b * xStride + n0;
    const int ty = t >> 4, tx = t & 15;

    unsigned long long acc[8][4];
#pragma unroll
    for (int i = 0; i < 8; i++)
#pragma unroll
        for (int j = 0; j < 4; j++) acc[i][j] = 0ull;

    for (int c0 = 0; c0 < CIN; c0 += 16) {
#pragma unroll
        for (int i = t; i < 2048; i += 256) {
            int k = i >> 7, o = i & 127;
            Ws[k][o] = W[o * CIN + c0 + k] * scale_s[o];
        }
#pragma unroll
        for (int i = t; i < 2048; i += 256) {
            int k = i >> 7, n = i & 127;
            Xs[k][n] = Xb[(size_t)(c0 + k) * NPIX + n];
        }
        __syncthreads();

#pragma unroll 4
        for (int k = 0; k < 16; k++) {
            float4 a0 = *(const float4*)&Ws[k][ty * 8];
            float4 a1 = *(const float4*)&Ws[k][ty * 8 + 4];
            unsigned long long ad[8] = {
                pk2(a0.x, a0.x), pk2(a0.y, a0.y), pk2(a0.z, a0.z), pk2(a0.w, a0.w),
                pk2(a1.x, a1.x), pk2(a1.y, a1.y), pk2(a1.z, a1.z), pk2(a1.w, a1.w)};
            unsigned long long bv[4];
#pragma unroll
            for (int j = 0; j < 4; j++)
                bv[j] = *(const unsigned long long*)&Xs[k][tx * 8 + 2 * j];
#pragma unroll
            for (int i = 0; i < 8; i++)
#pragma unroll
                for (int j = 0; j < 4; j++) fma2(acc[i][j], ad[i], bv[j]);
        }
        __syncthreads();
    }

    float* Yb = Y + (size_t)b * yStride + n0 + tx * 8;
#pragma unroll
    for (int i = 0; i < 8; i++) {
        int o = ty * 8 + i;
        float bi = bias_s[o];
        float2 p0 = up2(acc[i][0]), p1 = up2(acc[i][1]);
        float2 p2 = up2(acc[i][2]), p3 = up2(acc[i][3]);
        float4 r0 = make_float4(fmaxf(p0.x + bi, 0.f), fmaxf(p0.y + bi, 0.f),
                                fmaxf(p1.x + bi, 0.f), fmaxf(p1.y + bi, 0.f));
        float4 r1 = make_float4(fmaxf(p2.x + bi, 0.f), fmaxf(p2.y + bi, 0.f),
                                fmaxf(p3.x + bi, 0.f), fmaxf(p3.y + bi, 0.f));
        *(float4*)&Yb[(size_t)o * NPIX]     = r0;
        *(float4*)&Yb[(size_t)o * NPIX + 4] = r1;
    }
}

// ============================================================================
// conv_kq: K/Q = relu(BN(w_kq @ x_en/x_de)),  O = 32, CIN = 128
// ============================================================================
__global__ void __launch_bounds__(256) conv_kq_kernel(
    const float* __restrict__ Xen, const float* __restrict__ Xde,
    const float* __restrict__ W,
    const float* __restrict__ gam, const float* __restrict__ bet,
    const float* __restrict__ mean, const float* __restrict__ var)
{
    __shared__ __align__(16) float Ws[16][32];
    __shared__ __align__(16) float Xs[16][128];
    __shared__ float scale_s[32], bias_s[32];

    const int t  = threadIdx.x;
    const int b  = blockIdx.y;
    const int n0 = blockIdx.x * 128;
    const float* X = (blockIdx.z == 0) ? Xen : Xde;
    float* Y       = (blockIdx.z == 0) ? g_K : g_Q;

    if (t < 32) {
        float s = gam[t] * rsqrtf(var[t] + BN_EPS);
        scale_s[t] = s;
        bias_s[t]  = bet[t] - mean[t] * s;
    }
    __syncthreads();

    const float* Xb = X + (size_t)b * CC * NPIX + n0;
    const int ty = t >> 4, tx = t & 15;

    unsigned long long acc[2][4];
#pragma unroll
    for (int i = 0; i < 2; i++)
#pragma unroll
        for (int j = 0; j < 4; j++) acc[i][j] = 0ull;

    for (int c0 = 0; c0 < CC; c0 += 16) {
#pragma unroll
        for (int i = t; i < 512; i += 256) {
            int k = i >> 5, o = i & 31;
            Ws[k][o] = W[o * CC + c0 + k] * scale_s[o];
        }
#pragma unroll
        for (int i = t; i < 2048; i += 256) {
            int k = i >> 7, n = i & 127;
            Xs[k][n] = Xb[(size_t)(c0 + k) * NPIX + n];
        }
        __syncthreads();

#pragma unroll 4
        for (int k = 0; k < 16; k++) {
            float2 a = *(const float2*)&Ws[k][ty * 2];
            unsigned long long a0 = pk2(a.x, a.x);
            unsigned long long a1 = pk2(a.y, a.y);
            unsigned long long bv[4];
#pragma unroll
            for (int j = 0; j < 4; j++)
                bv[j] = *(const unsigned long long*)&Xs[k][tx * 8 + 2 * j];
#pragma unroll
            for (int j = 0; j < 4; j++) { fma2(acc[0][j], a0, bv[j]); fma2(acc[1][j], a1, bv[j]); }
        }
        __syncthreads();
    }

    float* Yb = Y + (size_t)b * C4C * NPIX + n0 + tx * 8;
#pragma unroll
    for (int i = 0; i < 2; i++) {
        int o = ty * 2 + i;
        float bi = bias_s[o];
        float2 p0 = up2(acc[i][0]), p1 = up2(acc[i][1]);
        float2 p2 = up2(acc[i][2]), p3 = up2(acc[i][3]);
        float4 r0 = make_float4(fmaxf(p0.x + bi, 0.f), fmaxf(p0.y + bi, 0.f),
                                fmaxf(p1.x + bi, 0.f), fmaxf(p1.y + bi, 0.f));
        float4 r1 = make_float4(fmaxf(p2.x + bi, 0.f), fmaxf(p2.y + bi, 0.f),
                                fmaxf(p3.x + bi, 0.f), fmaxf(p3.y + bi, 0.f));
        *(float4*)&Yb[(size_t)o * NPIX]     = r0;
        *(float4*)&Yb[(size_t)o * NPIX + 4] = r1;
    }
}

// ============================================================================
// kqgemm: KQ[b,n,m] = sum_k K[b,k,n]*Q[b,k,m]  (k depth = 32), fp32 SIMT.
// Stores raw KQ (streaming) + per-block (max, sumexp) partials.
// ============================================================================
__global__ void __launch_bounds__(256) kqgemm_kernel()
{
    __shared__ __align__(16) float Ks[32][128];
    __shared__ __align__(16) float Qs[32][128];

    const int t  = threadIdx.x;
    const int b  = blockIdx.z;
    const int n0 = blockIdx.y * 128;
    const int m0 = blockIdx.x * 128;

    const float* Kb = g_K + (size_t)b * C4C * NPIX;
    const float* Qb = g_Q + (size_t)b * C4C * NPIX;

#pragma unroll
    for (int i = t; i < 4096; i += 256) {
        int k = i >> 7, c = i & 127;
        Ks[k][c] = Kb[(size_t)k * NPIX + n0 + c];
        Qs[k][c] = Qb[(size_t)k * NPIX + m0 + c];
    }
    __syncthreads();

    const int ty = t >> 4, tx = t & 15;
    unsigned long long acc[8][4];
#pragma unroll
    for (int i = 0; i < 8; i++)
#pragma unroll
        for (int j = 0; j < 4; j++) acc[i][j] = 0ull;

#pragma unroll 4
    for (int k = 0; k < 32; k++) {
        float4 a0 = *(const float4*)&Ks[k][ty * 8];
        float4 a1 = *(const float4*)&Ks[k][ty * 8 + 4];
        unsigned long long ad[8] = {
            pk2(a0.x, a0.x), pk2(a0.y, a0.y), pk2(a0.z, a0.z), pk2(a0.w, a0.w),
            pk2(a1.x, a1.x), pk2(a1.y, a1.y), pk2(a1.z, a1.z), pk2(a1.w, a1.w)};
        unsigned long long bv[4];
#pragma unroll
        for (int j = 0; j < 4; j++)
            bv[j] = *(const unsigned long long*)&Qs[k][tx * 8 + 2 * j];
#pragma unroll
        for (int i = 0; i < 8; i++)
#pragma unroll
            for (int j = 0; j < 4; j++) fma2(acc[i][j], ad[i], bv[j]);
    }

    float vals[8][8];
    float vmax = -1e30f;
#pragma unroll
    for (int i = 0; i < 8; i++) {
#pragma unroll
        for (int j = 0; j < 4; j++) {
            float2 p = up2(acc[i][j]);
            vals[i][2 * j]     = p.x;
            vals[i][2 * j + 1] = p.y;
            vmax = fmaxf(vmax, fmaxf(p.x, p.y));
        }
    }
#pragma unroll
    for (int i = 0; i < 8; i++) {
        size_t off = (size_t)b * N2 + (size_t)(n0 + ty * 8 + i) * NPIX + m0 + tx * 8;
        __stcs((float4*)&g_KQ[off],
               make_float4(vals[i][0], vals[i][1], vals[i][2], vals[i][3]));
        __stcs((float4*)&g_KQ[off + 4],
               make_float4(vals[i][4], vals[i][5], vals[i][6], vals[i][7]));
    }
    float lt = 0.f;
#pragma unroll
    for (int i = 0; i < 8; i++)
#pragma unroll
        for (int j = 0; j < 8; j++) lt += __expf(vals[i][j] - vmax);

    __syncthreads();
    float* sm = (float*)Ks;
    float* sl = (float*)Qs;
    sm[t] = vmax; sl[t] = lt;
    __syncthreads();
    for (int s = 128; s > 0; s >>= 1) {
        if (t < s) {
            float m1 = sm[t], m2 = sm[t + s], l1 = sl[t], l2 = sl[t + s];
            float M = fmaxf(m1, m2);
            sl[t] = l1 * __expf(m1 - M) + l2 * __expf(m2 - M);
            sm[t] = M;
        }
        __syncthreads();
    }
    if (t == 0) {
        int pb = blockIdx.y * NT + blockIdx.x;
        g_pm[b * PB + pb] = sm[0];
        g_pl[b * PB + pb] = sl[0];
    }
}

// ============================================================================
// combine: reduce PB partials -> per-batch (M, Z).
// ============================================================================
__global__ void __launch_bounds__(512) combine_kernel()
{
    __shared__ float sm[512], sl[512];
    const int b = blockIdx.x, t = threadIdx.x;
    float m = -INFINITY, l = 0.f;
    if (t < PB) { m = g_pm[b * PB + t]; l = g_pl[b * PB + t]; }
    sm[t] = m; sl[t] = l;
    __syncthreads();
    for (int s = 256; s > 0; s >>= 1) {
        if (t < s) {
            float m1 = sm[t], m2 = sm[t + s], l1 = sl[t], l2 = sl[t + s];
            float M = fmaxf(m1, m2);
            float L;
            if (M == -INFINITY) L = 0.f;
            else L = (m1 == -INFINITY ? 0.f : l1 * __expf(m1 - M))
                   + (m2 == -INFINITY ? 0.f : l2 * __expf(m2 - M));
            sm[t] = M; sl[t] = L;
        }
        __syncthreads();
    }
    if (t == 0) { g_M[b] = sm[0]; g_Z[b] = sl[0]; }
}

// ============================================================================
// feat: feat[b,c,n] = (1/Z) * sum_m V[b,c,m] * exp(KQ[b,n,m] - M)
// sm_103a pass: tcgen05 kind::tf32 SS MMA, 2-stage SMEM ring.
// compute_103 pass: SIMT f32x2 fallback (same dynamic smem footprint).
// grid: (NT, B), 256 threads, dynamic smem.
// ============================================================================
#define FT_NST    2
#define FT_NCHUNK 72                    // 2304 / 32
#define FT_STAGE_BYTES 16384            // 128 rows * 128B
#define FT_SMEM_TOTAL (1024 + 2 * FT_NST * FT_STAGE_BYTES)   // 66560

__global__ void __launch_bounds__(256) feat_kernel(float* __restrict__ out)
{
    extern __shared__ __align__(16) char smem[];
    const int t  = threadIdx.x;
    const int b  = blockIdx.y;
    const int n0 = blockIdx.x * 128;

    const float Mb   = g_M[b];
    const float invZ = 1.f / g_Z[b];

#if HAS_TC
    // ---------------- tensor-core path ----------------
    const uint32_t sb     = smem_to_u32(smem);
    const uint32_t base1k = (sb + 64 + 1023) & ~1023u;           // A stages
    const uint32_t bbase0 = base1k + FT_NST * FT_STAGE_BYTES;    // B stages
    const int wid = t >> 5;

    if (wid == 0) TCGEN05_ALLOC(sb + 0, 128);
    if (t == 0) {
#pragma unroll
        for (int s = 0; s < FT_NST; s++) MBARRIER_INIT(sb + 16 + 8 * s, 1);
    }
    __syncthreads();

    uint32_t tmem;
    asm volatile("ld.shared.b32 %0, [%1];" : "=r"(tmem) : "r"(sb));

    const int r = t >> 1, h = t & 1;
    const float* Vrow = g_V  + (size_t)b * CC * NPIX + (size_t)r * NPIX + h * 16;
    const float* Krow = g_KQ + (size_t)b * N2 + (size_t)(n0 + r) * NPIX + h * 16;
    const uint32_t rowoff = (uint32_t)r * 128 + (uint32_t)h * 64;

    float4 vcur[4], kcur[4];
#pragma unroll
    for (int q = 0; q < 4; q++) {
        vcur[q] = *(const float4*)(Vrow + q * 4);
        kcur[q] = __ldcs((const float4*)(Krow + q * 4));
    }

    for (int i = 0; i < FT_NCHUNK; i++) {
        const int s = i & (FT_NST - 1);
        float4 vnx[4], knx[4];
        if (i < FT_NCHUNK - 1) {
            const float* Vp = Vrow + (i + 1) * 32;
            const float* Kp = Krow + (i + 1) * 32;
#pragma unroll
            for (int q = 0; q < 4; q++) {
                vnx[q] = *(const float4*)(Vp + q * 4);
                knx[q] = __ldcs((const float4*)(Kp + q * 4));
            }
        }
        if (i >= FT_NST) {
            uint32_t j = (uint32_t)(i >> 1);
            MBARRIER_WAIT_PARITY(sb + 16 + 8 * s, (j - 1) & 1u);
        }
        const uint32_t abase = base1k + s * FT_STAGE_BYTES;
        const uint32_t bbase = bbase0 + s * FT_STAGE_BYTES;
#pragma unroll
        for (int q = 0; q < 4; q++) {
            uint32_t off = rowoff + q * 16;
            uint32_t sw  = off ^ ((off >> 3) & 0x70);
            float4 v = vcur[q];
            float vx = tf32r(v.x), vy = tf32r(v.y), vz = tf32r(v.z), vw = tf32r(v.w);
            asm volatile("st.shared.v4.b32 [%0], {%1,%2,%3,%4};"
                :: "r"(abase + sw), "f"(vx), "f"(vy), "f"(vz), "f"(vw) : "memory");
            float4 kq = kcur[q];
            float px = tf32r(__expf(kq.x - Mb));
            float py = tf32r(__expf(kq.y - Mb));
            float pz = tf32r(__expf(kq.z - Mb));
            float pw = tf32r(__expf(kq.w - Mb));
            asm volatile("st.shared.v4.b32 [%0], {%1,%2,%3,%4};"
                :: "r"(bbase + sw), "f"(px), "f"(py), "f"(pz), "f"(pw) : "memory");
        }
        asm volatile("fence.proxy.async.shared::cta;" ::: "memory");
        __syncthreads();

        if (wid == 0) {
            if (elect_one_pred()) {
                uint64_t ad = MAKE_SMEM_DESC(abase);
                uint64_t bd = MAKE_SMEM_DESC(bbase);
#pragma unroll
                for (int kk = 0; kk < 4; kk++)
                    mma_tf32_ss(tmem, ad + 2 * kk, bd + 2 * kk, IDESC_TF32,
                                (i > 0) || (kk > 0));
                TCGEN05_COMMIT(sb + 16 + 8 * s);
            }
        }
#pragma unroll
        for (int q = 0; q < 4; q++) { vcur[q] = vnx[q]; kcur[q] = knx[q]; }
    }

    // last commit: stage (71&1)=1, its 36th use -> completes phase 35 -> parity 1
    MBARRIER_WAIT_PARITY(sb + 16 + 8 * 1, 1u);
    TCGEN05_FENCE_AFTER();

    if (t < 128) {
        const int c = t;
        float* Ob = out + (size_t)b * (2 * CC) * NPIX + (size_t)(CC + c) * NPIX + n0;
#pragma unroll
        for (int cb = 0; cb < 128; cb += 32) {
            uint32_t regs[32];
            TCGEN05_LD_32X32B_X32(regs, tmem + cb);
            TCGEN05_WAIT_LD();
#pragma unroll
            for (int j = 0; j < 32; j++)
                Ob[cb + j] = __uint_as_float(regs[j]) * invZ;
        }
    }
    __syncthreads();
    if (wid == 0) TCGEN05_DEALLOC(tmem, 128);

#else
    // ---------------- SIMT f32x2 fallback (compute_103 pass) ----------------
    float* Vs = (float*)smem;            // [32][132]
    float* Ps = Vs + 32 * 132;           // [32][132]

    const int ty = t >> 4, tx = t & 15;

    unsigned long long acc[8][4];
#pragma unroll
    for (int i = 0; i < 8; i++)
#pragma unroll
        for (int j = 0; j < 4; j++) acc[i][j] = 0ull;

    const float* Vb  = g_V  + (size_t)b * CC * NPIX;
    const float* KQb = g_KQ + (size_t)b * N2 + (size_t)n0 * NPIX;

    for (int m0 = 0; m0 < NPIX; m0 += 32) {
#pragma unroll
        for (int i = t; i < 1024; i += 256) {
            int r = i >> 3, q = i & 7;
            float4 v = *(const float4*)&Vb[(size_t)r * NPIX + m0 + q * 4];
            Vs[(q * 4 + 0) * 132 + r] = v.x; Vs[(q * 4 + 1) * 132 + r] = v.y;
            Vs[(q * 4 + 2) * 132 + r] = v.z; Vs[(q * 4 + 3) * 132 + r] = v.w;
            float4 kq = __ldcs((const float4*)&KQb[(size_t)r * NPIX + m0 + q * 4]);
            Ps[(q * 4 + 0) * 132 + r] = __expf(kq.x - Mb);
            Ps[(q * 4 + 1) * 132 + r] = __expf(kq.y - Mb);
            Ps[(q * 4 + 2) * 132 + r] = __expf(kq.z - Mb);
            Ps[(q * 4 + 3) * 132 + r] = __expf(kq.w - Mb);
        }
        __syncthreads();

#pragma unroll 4
        for (int k = 0; k < 32; k++) {
            float4 a0 = *(const float4*)&Vs[k * 132 + ty * 8];
            float4 a1 = *(const float4*)&Vs[k * 132 + ty * 8 + 4];
            unsigned long long ad[8] = {
                pk2(a0.x, a0.x), pk2(a0.y, a0.y), pk2(a0.z, a0.z), pk2(a0.w, a0.w),
                pk2(a1.x, a1.x), pk2(a1.y, a1.y), pk2(a1.z, a1.z), pk2(a1.w, a1.w)};
            unsigned long long bv[4];
#pragma unroll
            for (int j = 0; j < 4; j++)
                bv[j] = *(const unsigned long long*)&Ps[k * 132 + tx * 8 + 2 * j];
#pragma unroll
            for (int i = 0; i < 8; i++)
#pragma unroll
                for (int j = 0; j < 4; j++) fma2(acc[i][j], ad[i], bv[j]);
        }
        __syncthreads();
    }

    float* Ob = out + (size_t)b * (2 * CC) * NPIX + (size_t)CC * NPIX + n0 + tx * 8;
#pragma unroll
    for (int i = 0; i < 8; i++) {
        int c = ty * 8 + i;
        float2 p0 = up2(acc[i][0]), p1 = up2(acc[i][1]);
        float2 p2 = up2(acc[i][2]), p3 = up2(acc[i][3]);
        float4 r0 = make_float4(p0.x * invZ, p0.y * invZ, p1.x * invZ, p1.y * invZ);
        float4 r1 = make_float4(p2.x * invZ, p2.y * invZ, p3.x * invZ, p3.y * invZ);
        *(float4*)&Ob[(size_t)c * NPIX]     = r0;
        *(float4*)&Ob[(size_t)c * NPIX + 4] = r1;
    }
#endif
}

// ============================================================================
// launch
// ============================================================================
extern "C" void kernel_launch(void* const* d_in, const int* in_sizes, int n_in,
                              void* d_out, int out_size)
{
    const float* x_en   = (const float*)d_in[0];
    const float* x_de   = (const float*)d_in[1];
    const float* x_cat  = (const float*)d_in[2];
    const float* w_kq   = (const float*)d_in[3];
    const float* kq_g   = (const float*)d_in[4];
    const float* kq_b   = (const float*)d_in[5];
    const float* kq_m   = (const float*)d_in[6];
    const float* kq_v   = (const float*)d_in[7];
    const float* w_v    = (const float*)d_in[8];
    const float* v_g    = (const float*)d_in[9];
    const float* v_b    = (const float*)d_in[10];
    const float* v_m    = (const float*)d_in[11];
    const float* v_v    = (const float*)d_in[12];
    const float* w_red  = (const float*)d_in[13];
    const float* red_g  = (const float*)d_in[14];
    const float* red_b  = (const float*)d_in[15];
    const float* red_m  = (const float*)d_in[16];
    const float* red_v  = (const float*)d_in[17];
    float* out = (float*)d_out;

    float* pV = nullptr;
    cudaGetSymbolAddress((void**)&pV, g_V);

    cudaFuncSetAttribute(feat_kernel,
                         cudaFuncAttributeMaxDynamicSharedMemorySize, FT_SMEM_TOTAL);

    const size_t twoCN = (size_t)2 * CC * NPIX;
    const size_t CN    = (size_t)CC * NPIX;

    // x = relu(BN(w_red @ x_cat)) -> output channels [0, C)
    conv128_kernel<<<dim3(NT, BB), 256>>>(x_cat, twoCN, 2 * CC, w_red,
                                          red_g, red_b, red_m, red_v,
                                          out, twoCN);
    // V = relu(BN(w_v @ x))
    conv128_kernel<<<dim3(NT, BB), 256>>>(out, twoCN, CC, w_v,
                                          v_g, v_b, v_m, v_v,
                                          pV, CN);
    // K, Q
    conv_kq_kernel<<<dim3(NT, BB, 2), 256>>>(x_en, x_de, w_kq,
                                             kq_g, kq_b, kq_m, kq_v);
    // KQ + per-block logsumexp partials
    kqgemm_kernel<<<dim3(NT, NT, BB), 256>>>();
    // per-batch (M, Z)
    combine_kernel<<<BB, 512>>>();
    // feat -> output channels [C, 2C)
    feat_kernel<<<dim3(NT, BB), 256, FT_SMEM_TOTAL>>>(out);
}